// round 3
// baseline (speedup 1.0000x reference)
#include <cuda_runtime.h>

// Fixed shapes: v, v_pred are [4, 8192, 3] fp32
#define BATCH 4
#define NPTS  8192
#define JS    16                // reduction-dim splits
#define SEG   (NPTS / JS)       // 512 y-points per segment
#define XC    4                 // x chunks per batch (2048 pts each)
#define T1    256               // threads, kernel 1
#define XPT   8                 // query points per thread (4 f32x2 pairs)
#define NPAIR (XPT / 2)

// Scratch: partial mins [BATCH][JS][NPTS] (2 MB) + per-block sums (128 floats)
__device__ float g_partial[BATCH * JS * NPTS];
__device__ float g_bsum[128];

// ---- packed f32x2 helpers (SASS FFMA2 — only reachable via PTX) -----------
__device__ __forceinline__ unsigned long long pack2(float lo, float hi) {
    unsigned long long r;
    asm("mov.b64 %0, {%1, %2};" : "=l"(r) : "f"(lo), "f"(hi));
    return r;
}
__device__ __forceinline__ unsigned long long fma2(unsigned long long a,
                                                   unsigned long long b,
                                                   unsigned long long c) {
    unsigned long long d;
    asm("fma.rn.f32x2 %0, %1, %2, %3;" : "=l"(d) : "l"(a), "l"(b), "l"(c));
    return d;
}
__device__ __forceinline__ void unpack2(unsigned long long v, float& lo, float& hi) {
    asm("mov.b64 {%0, %1}, %2;" : "=f"(lo), "=f"(hi) : "l"(v));
}

// ---------------------------------------------------------------------------
// Kernel 1: per (batch, x-chunk, y-segment) partial min of (|y|^2 - 2 x.y).
// y stored in smem pre-duplicated for f32x2: (y0,y0,y1,y1) / (y2,y2,w,w).
// Inner loop per j: 2x LDS.128 (broadcast) + 4 pairs x (3 FFMA2 + 2 FMNMX).
// ---------------------------------------------------------------------------
__global__ __launch_bounds__(T1) void chamfer_partial_kernel(
    const float* __restrict__ v,       // y / target  [B, N, 3]
    const float* __restrict__ v_pred)  // x / queries [B, N, 3]
{
    __shared__ float4 ys[SEG * 2];

    const int blk = blockIdx.x;           // 0 .. 255
    const int b   = blk >> 6;             // / (XC*JS)
    const int rem = blk & 63;
    const int xc  = rem >> 4;
    const int js  = rem & 15;

    const float* __restrict__ yb = v      + (size_t)b * NPTS * 3;
    const float* __restrict__ xb = v_pred + (size_t)b * NPTS * 3;

    // Stage y segment, duplicated per component
    for (int t = threadIdx.x; t < SEG; t += T1) {
        const int j = js * SEG + t;
        const float y0 = __ldg(&yb[j * 3 + 0]);
        const float y1 = __ldg(&yb[j * 3 + 1]);
        const float y2 = __ldg(&yb[j * 3 + 2]);
        const float w  = fmaf(y0, y0, fmaf(y1, y1, y2 * y2));
        ys[2 * t + 0] = make_float4(y0, y0, y1, y1);
        ys[2 * t + 1] = make_float4(y2, y2, w, w);
    }
    __syncthreads();

    // Register-tile XPT query points as NPAIR f32x2 pairs
    unsigned long long a0[NPAIR], a1[NPAIR], a2[NPAIR];
    float c[XPT], m[XPT];
    const int i0 = xc * (T1 * XPT) + threadIdx.x;
#pragma unroll
    for (int pr = 0; pr < NPAIR; pr++) {
        float p0[2], p1[2], p2[2];
#pragma unroll
        for (int h = 0; h < 2; h++) {
            const int k = 2 * pr + h;
            const int i = i0 + k * T1;
            p0[h] = __ldg(&xb[i * 3 + 0]);
            p1[h] = __ldg(&xb[i * 3 + 1]);
            p2[h] = __ldg(&xb[i * 3 + 2]);
            c[k]  = fmaf(p0[h], p0[h], fmaf(p1[h], p1[h], p2[h] * p2[h]));
            m[k]  = 3.402823466e38f;
        }
        a0[pr] = pack2(-2.0f * p0[0], -2.0f * p0[1]);
        a1[pr] = pack2(-2.0f * p1[0], -2.0f * p1[1]);
        a2[pr] = pack2(-2.0f * p2[0], -2.0f * p2[1]);
    }

    const ulonglong2* __restrict__ ysp = reinterpret_cast<const ulonglong2*>(ys);
#pragma unroll 2
    for (int j = 0; j < SEG; j++) {
        const ulonglong2 q0 = ysp[2 * j + 0];   // (y0,y0) , (y1,y1)
        const ulonglong2 q1 = ysp[2 * j + 1];   // (y2,y2) , (w,w)
#pragma unroll
        for (int pr = 0; pr < NPAIR; pr++) {
            unsigned long long d = fma2(a2[pr], q1.x, q1.y);
            d = fma2(a1[pr], q0.y, d);
            d = fma2(a0[pr], q0.x, d);
            float dl, dh;
            unpack2(d, dl, dh);
            m[2 * pr + 0] = fminf(m[2 * pr + 0], dl);
            m[2 * pr + 1] = fminf(m[2 * pr + 1], dh);
        }
    }

    float* __restrict__ out = g_partial + (size_t)(b * JS + js) * NPTS;
#pragma unroll
    for (int k = 0; k < XPT; k++)
        out[i0 + k * T1] = m[k] + c[k];   // coalesced (stride T1)
}

// ---------------------------------------------------------------------------
// Kernel 2: 128 blocks. Each block: min across JS segments for 256 contiguous
// query points (coalesced, L2-resident), then block-sum -> g_bsum[blk].
// ---------------------------------------------------------------------------
__global__ __launch_bounds__(256) void chamfer_minsum_kernel()
{
    const int t   = threadIdx.x;
    const int blk = blockIdx.x;            // 0..127
    const int b   = blk >> 5;              // 32 blocks per batch
    const int i   = (blk & 31) * 256 + t;  // point index within batch

    const float* __restrict__ base = g_partial + (size_t)b * JS * NPTS + i;
    float mn = 3.402823466e38f;
#pragma unroll
    for (int js = 0; js < JS; js++)
        mn = fminf(mn, base[(size_t)js * NPTS]);

    // block sum
    float s = mn;
#pragma unroll
    for (int o = 16; o > 0; o >>= 1)
        s += __shfl_down_sync(0xffffffffu, s, o);

    __shared__ float ws[8];
    const int lane = t & 31, wid = t >> 5;
    if (lane == 0) ws[wid] = s;
    __syncthreads();
    if (wid == 0) {
        float v2 = (lane < 8) ? ws[lane] : 0.0f;
#pragma unroll
        for (int o = 4; o > 0; o >>= 1)
            v2 += __shfl_down_sync(0xffffffffu, v2, o);
        if (lane == 0) g_bsum[blk] = v2;
    }
}

// ---------------------------------------------------------------------------
// Kernel 3: single tiny block sums the 128 block partials -> mean.
// ---------------------------------------------------------------------------
__global__ __launch_bounds__(128) void chamfer_final_kernel(float* __restrict__ out)
{
    const int t = threadIdx.x;
    float s = g_bsum[t];
#pragma unroll
    for (int o = 16; o > 0; o >>= 1)
        s += __shfl_down_sync(0xffffffffu, s, o);

    __shared__ float ws[4];
    const int lane = t & 31, wid = t >> 5;
    if (lane == 0) ws[wid] = s;
    __syncthreads();
    if (t == 0) {
        const float tot = ws[0] + ws[1] + ws[2] + ws[3];
        out[0] = tot * (1.0f / (float)(BATCH * NPTS));
    }
}

// ---------------------------------------------------------------------------
extern "C" void kernel_launch(void* const* d_in, const int* in_sizes, int n_in,
                              void* d_out, int out_size)
{
    const float* v      = (const float*)d_in[0];   // target set (y)
    const float* v_pred = (const float*)d_in[1];   // query set  (x)
    float* out = (float*)d_out;

    chamfer_partial_kernel<<<BATCH * XC * JS, T1>>>(v, v_pred);
    chamfer_minsum_kernel<<<128, 256>>>();
    chamfer_final_kernel<<<1, 128>>>(out);
}

// round 4
// speedup vs baseline: 1.1298x; 1.1298x over previous
#include <cuda_runtime.h>

// Fixed shapes: v, v_pred are [4, 8192, 3] fp32
#define BATCH 4
#define NPTS  8192
#define JS    32                // reduction-dim splits (TLP knob)
#define SEG   (NPTS / JS)       // 256 y-points per segment
#define XC    8                 // x chunks per batch (1024 pts each)
#define T1    128               // threads, kernel 1
#define XPT   8                 // query points per thread (4 f32x2 pairs)
#define NPAIR (XPT / 2)

// Scratch: partial mins [BATCH][JS][NPTS] (4 MB) + per-block sums (128 floats)
__device__ float g_partial[BATCH * JS * NPTS];
__device__ float g_bsum[128];

// ---- packed f32x2 helpers (SASS FFMA2 — only reachable via PTX) -----------
__device__ __forceinline__ unsigned long long pack2(float lo, float hi) {
    unsigned long long r;
    asm("mov.b64 %0, {%1, %2};" : "=l"(r) : "f"(lo), "f"(hi));
    return r;
}
__device__ __forceinline__ unsigned long long fma2(unsigned long long a,
                                                   unsigned long long b,
                                                   unsigned long long c) {
    unsigned long long d;
    asm("fma.rn.f32x2 %0, %1, %2, %3;" : "=l"(d) : "l"(a), "l"(b), "l"(c));
    return d;
}
__device__ __forceinline__ void unpack2(unsigned long long v, float& lo, float& hi) {
    asm("mov.b64 {%0, %1}, %2;" : "=f"(lo), "=f"(hi) : "l"(v));
}

// ---------------------------------------------------------------------------
// Kernel 1: per (batch, x-chunk, y-segment) partial min of (|y|^2 - 2 x.y).
// y stored in smem pre-duplicated for f32x2: (y0,y0,y1,y1) / (y2,y2,w,w).
// Inner loop per j: 2x LDS.128 (broadcast) + 4 pairs x (3 FFMA2 + 2 FMNMX).
// 1024 blocks x 4 warps -> ~28 warps/SM, single wave, all co-resident.
// ---------------------------------------------------------------------------
__global__ __launch_bounds__(T1, 8) void chamfer_partial_kernel(
    const float* __restrict__ v,       // y / target  [B, N, 3]
    const float* __restrict__ v_pred)  // x / queries [B, N, 3]
{
    __shared__ float4 ys[SEG * 2];     // 8 KB

    const int blk = blockIdx.x;           // 0 .. 1023
    const int b   = blk >> 8;             // / (XC*JS)
    const int rem = blk & 255;
    const int xc  = rem >> 5;
    const int js  = rem & 31;

    const float* __restrict__ yb = v      + (size_t)b * NPTS * 3;
    const float* __restrict__ xb = v_pred + (size_t)b * NPTS * 3;

    // Stage y segment, duplicated per component
    for (int t = threadIdx.x; t < SEG; t += T1) {
        const int j = js * SEG + t;
        const float y0 = __ldg(&yb[j * 3 + 0]);
        const float y1 = __ldg(&yb[j * 3 + 1]);
        const float y2 = __ldg(&yb[j * 3 + 2]);
        const float w  = fmaf(y0, y0, fmaf(y1, y1, y2 * y2));
        ys[2 * t + 0] = make_float4(y0, y0, y1, y1);
        ys[2 * t + 1] = make_float4(y2, y2, w, w);
    }
    __syncthreads();

    // Register-tile XPT query points as NPAIR f32x2 pairs
    unsigned long long a0[NPAIR], a1[NPAIR], a2[NPAIR];
    float c[XPT], m[XPT];
    const int i0 = xc * (T1 * XPT) + threadIdx.x;
#pragma unroll
    for (int pr = 0; pr < NPAIR; pr++) {
        float p0[2], p1[2], p2[2];
#pragma unroll
        for (int h = 0; h < 2; h++) {
            const int k = 2 * pr + h;
            const int i = i0 + k * T1;
            p0[h] = __ldg(&xb[i * 3 + 0]);
            p1[h] = __ldg(&xb[i * 3 + 1]);
            p2[h] = __ldg(&xb[i * 3 + 2]);
            c[k]  = fmaf(p0[h], p0[h], fmaf(p1[h], p1[h], p2[h] * p2[h]));
            m[k]  = 3.402823466e38f;
        }
        a0[pr] = pack2(-2.0f * p0[0], -2.0f * p0[1]);
        a1[pr] = pack2(-2.0f * p1[0], -2.0f * p1[1]);
        a2[pr] = pack2(-2.0f * p2[0], -2.0f * p2[1]);
    }

    const ulonglong2* __restrict__ ysp = reinterpret_cast<const ulonglong2*>(ys);
#pragma unroll 2
    for (int j = 0; j < SEG; j++) {
        const ulonglong2 q0 = ysp[2 * j + 0];   // (y0,y0) , (y1,y1)
        const ulonglong2 q1 = ysp[2 * j + 1];   // (y2,y2) , (w,w)
#pragma unroll
        for (int pr = 0; pr < NPAIR; pr++) {
            unsigned long long d = fma2(a2[pr], q1.x, q1.y);
            d = fma2(a1[pr], q0.y, d);
            d = fma2(a0[pr], q0.x, d);
            float dl, dh;
            unpack2(d, dl, dh);
            m[2 * pr + 0] = fminf(m[2 * pr + 0], dl);
            m[2 * pr + 1] = fminf(m[2 * pr + 1], dh);
        }
    }

    float* __restrict__ out = g_partial + (size_t)(b * JS + js) * NPTS;
#pragma unroll
    for (int k = 0; k < XPT; k++)
        out[i0 + k * T1] = m[k] + c[k];   // coalesced (stride T1)
}

// ---------------------------------------------------------------------------
// Kernel 2: 128 blocks. Each thread: min across JS segments for one query
// point (coalesced, L2-resident), then block-sum -> g_bsum[blk].
// ---------------------------------------------------------------------------
__global__ __launch_bounds__(256) void chamfer_minsum_kernel()
{
    const int t   = threadIdx.x;
    const int blk = blockIdx.x;            // 0..127
    const int b   = blk >> 5;              // 32 blocks per batch
    const int i   = (blk & 31) * 256 + t;  // point index within batch

    const float* __restrict__ base = g_partial + (size_t)b * JS * NPTS + i;
    float mn = 3.402823466e38f;
#pragma unroll
    for (int js = 0; js < JS; js++)
        mn = fminf(mn, base[(size_t)js * NPTS]);

    // block sum
    float s = mn;
#pragma unroll
    for (int o = 16; o > 0; o >>= 1)
        s += __shfl_down_sync(0xffffffffu, s, o);

    __shared__ float ws[8];
    const int lane = t & 31, wid = t >> 5;
    if (lane == 0) ws[wid] = s;
    __syncthreads();
    if (wid == 0) {
        float v2 = (lane < 8) ? ws[lane] : 0.0f;
#pragma unroll
        for (int o = 4; o > 0; o >>= 1)
            v2 += __shfl_down_sync(0xffffffffu, v2, o);
        if (lane == 0) g_bsum[blk] = v2;
    }
}

// ---------------------------------------------------------------------------
// Kernel 3: single tiny block sums the 128 block partials -> mean.
// ---------------------------------------------------------------------------
__global__ __launch_bounds__(128) void chamfer_final_kernel(float* __restrict__ out)
{
    const int t = threadIdx.x;
    float s = g_bsum[t];
#pragma unroll
    for (int o = 16; o > 0; o >>= 1)
        s += __shfl_down_sync(0xffffffffu, s, o);

    __shared__ float ws[4];
    const int lane = t & 31, wid = t >> 5;
    if (lane == 0) ws[wid] = s;
    __syncthreads();
    if (t == 0) {
        const float tot = ws[0] + ws[1] + ws[2] + ws[3];
        out[0] = tot * (1.0f / (float)(BATCH * NPTS));
    }
}

// ---------------------------------------------------------------------------
extern "C" void kernel_launch(void* const* d_in, const int* in_sizes, int n_in,
                              void* d_out, int out_size)
{
    const float* v      = (const float*)d_in[0];   // target set (y)
    const float* v_pred = (const float*)d_in[1];   // query set  (x)
    float* out = (float*)d_out;

    chamfer_partial_kernel<<<BATCH * XC * JS, T1>>>(v, v_pred);
    chamfer_minsum_kernel<<<128, 256>>>();
    chamfer_final_kernel<<<1, 128>>>(out);
}